// round 11
// baseline (speedup 1.0000x reference)
#include <cuda_runtime.h>
#include <cstdint>

typedef unsigned long long ull;

#define SEQ   512
#define BATCH 64
#define DIN   256
#define HID   1024
#define SBH   (SEQ*BATCH*HID)

// ---------------- persistent-kernel geometry ----------------
#define NBLK 128          // 64 j-tiles x 2 batch-groups, 1 block/SM
#define GRP  64           // blocks per batch group
#define BT   32           // batch rows per block
#define JT   16           // hidden cols per block
#define WSP  18           // Ws2 stride (ull) per k-pair (proven conflict-free)
#define RSP  520          // reduction slice stride (floats)
#define HROW 260          // chunk row stride (floats): 260%32=4 -> 8 q-rows spread bank groups
#define CSLOT (BT*HROW)   // floats per k-chunk buffer
#define NCHUNK 4

#define OFF_MBAR 0                           // 4 mbarriers
#define OFF_W    128
#define OFF_RED  (OFF_W + 512*WSP*8)         // 128 + 73728 = 73856
#define OFF_H    (OFF_RED + 8*RSP*4)         // + 16640 = 90496
#define SMEM_BYTES (OFF_H + NCHUNK*CSLOT*4)  // + 133120 = 223616

// ---------------- device state ----------------
__device__ float g_h[2][BATCH*HID];   // ping-pong hidden state (L2-resident)
__device__ unsigned g_flags[NBLK];    // per-block completed-step counters

// ---------------- f32x2 helpers ----------------
__device__ __forceinline__ ull ffma2(ull a, ull b, ull c) {
    ull d; asm("fma.rn.f32x2 %0, %1, %2, %3;" : "=l"(d) : "l"(a), "l"(b), "l"(c)); return d;
}
__device__ __forceinline__ ull pk2(float x, float y) {
    ull r; asm("mov.b64 %0, {%1, %2};" : "=l"(r) : "f"(x), "f"(y)); return r;
}
__device__ __forceinline__ float2 upk(ull v) {
    float2 r; asm("mov.b64 {%0, %1}, %2;" : "=f"(r.x), "=f"(r.y) : "l"(v)); return r;
}

// ---------------- init: h0 = 0, flags = 0 ----------------
__global__ void init_kernel() {
    int i = blockIdx.x * blockDim.x + threadIdx.x;
    if (i < BATCH*HID) g_h[0][i] = 0.0f;
    if (i < NBLK) g_flags[i] = 0u;
}

// ---------------- phase 1: xp = x @ W_in^T + bias (into d_out) ----------------
#define P1_BM 128
#define P1_BN 64
#define P1_BK 16

__global__ __launch_bounds__(256) void xproj_kernel(
        const float* __restrict__ x, const float* __restrict__ Win,
        const float* __restrict__ bias, float* __restrict__ out) {
    __shared__ ull As[P1_BM][9];
    __shared__ ull Bs[P1_BN][9];

    const int t  = threadIdx.x;
    const int m0 = blockIdx.y * P1_BM;
    const int n0 = blockIdx.x * P1_BN;
    const int tm = t >> 4;
    const int tn = t & 15;

    ull acc[8][4];
    #pragma unroll
    for (int i = 0; i < 8; i++)
        #pragma unroll
        for (int j = 0; j < 4; j++) acc[i][j] = 0ull;

    for (int k0 = 0; k0 < DIN; k0 += P1_BK) {
        #pragma unroll
        for (int l = 0; l < 2; l++) {
            int idx = t + l * 256;
            int r = idx >> 2, c = idx & 3;
            float4 v = *reinterpret_cast<const float4*>(x + (size_t)(m0 + r) * DIN + k0 + c * 4);
            As[r][c*2]   = pk2(v.x, v.y);
            As[r][c*2+1] = pk2(v.z, v.w);
        }
        {
            int r = t >> 2, c = t & 3;
            float4 v = *reinterpret_cast<const float4*>(Win + (size_t)(n0 + r) * DIN + k0 + c * 4);
            Bs[r][c*2]   = pk2(v.x, v.y);
            Bs[r][c*2+1] = pk2(v.z, v.w);
        }
        __syncthreads();
        #pragma unroll
        for (int kp = 0; kp < 8; kp++) {
            ull a[8], b[4];
            #pragma unroll
            for (int i = 0; i < 8; i++) a[i] = As[tm + 16*i][kp];
            #pragma unroll
            for (int j = 0; j < 4; j++) b[j] = Bs[tn + 16*j][kp];
            #pragma unroll
            for (int i = 0; i < 8; i++)
                #pragma unroll
                for (int j = 0; j < 4; j++)
                    acc[i][j] = ffma2(a[i], b[j], acc[i][j]);
        }
        __syncthreads();
    }
    #pragma unroll
    for (int i = 0; i < 8; i++) {
        int m = m0 + tm + 16*i;
        #pragma unroll
        for (int j = 0; j < 4; j++) {
            int n = n0 + tn + 16*j;
            float2 s = upk(acc[i][j]);
            out[(size_t)m * HID + n] = s.x + s.y + bias[n];
        }
    }
}

// ---------------- mbarrier wait ----------------
__device__ __forceinline__ void mbar_wait(uint32_t mbar, uint32_t parity) {
    uint32_t done;
    do {
        asm volatile(
            "{\n\t.reg .pred p;\n\t"
            "mbarrier.try_wait.parity.acquire.cta.shared::cta.b64 p, [%1], %2, 0x989680;\n\t"
            "selp.b32 %0, 1, 0, p;\n\t}"
            : "=r"(done) : "r"(mbar), "r"(parity) : "memory");
    } while (!done);
}

// ---------------- phase 2: persistent recurrent kernel ----------------
__global__ __launch_bounds__(256, 1) void rnn_kernel(
        const float* __restrict__ Whh, const float* __restrict__ alpha,
        float* __restrict__ out, int write_hn) {
    extern __shared__ char sm[];
    const uint32_t smb = (uint32_t)__cvta_generic_to_shared(sm);
    ull*   Ws2 = reinterpret_cast<ull*>(sm + OFF_W);
    float* red = reinterpret_cast<float*>(sm + OFF_RED);
    float* hs  = reinterpret_cast<float*>(sm + OFF_H);
    const uint32_t mbar0 = smb + OFF_MBAR;
    const uint32_t hs_sm = smb + OFF_H;

    const int t   = threadIdx.x;
    const int bid = blockIdx.x;
    const int jtb = bid & 63;
    const int grp = bid >> 6;
    const int j0  = jtb * JT;
    const int b0g = grp * BT;

    if (t < NCHUNK)
        asm volatile("mbarrier.init.shared.b64 [%0], 1;" :: "r"(mbar0 + 8*t) : "memory");
    __syncthreads();

    // Load W_hh slice: Ws2[kp*WSP + jl] = {W[j0+jl][2kp], W[j0+jl][2kp+1]}
    #pragma unroll
    for (int l = 0; l < 32; l++) {
        int idx = t + l * 256;
        int jl  = idx >> 9;
        int kp  = idx & 511;
        float2 v = *reinterpret_cast<const float2*>(Whh + (size_t)(j0 + jl) * HID + 2 * kp);
        Ws2[kp * WSP + jl] = pk2(v.x, v.y);
    }

    // compute mapping: warp w = k-slice [128w,128w+128); lane -> (q rows, jt4 cols)
    const int w   = t >> 5;
    const int l   = t & 31;
    const int q   = l & 7;                 // rows q+8m
    const int jt4 = l >> 3;                // cols 4*jt4..+3
    const int mychunk = w >> 1;            // staged chunk this warp consumes
    const bool is_stager = ((w & 1) == 0); // warps 0,2,4,6 stage chunks 0..3

    const ull*   wpB = Ws2 + (size_t)w * 64 * WSP + 4 * jt4;
    const float* hqB = hs + mychunk * CSLOT + q * HROW + 128 * (w & 1);

    // epilogue mapping: 2 outputs per thread, h_prev in registers
    const int re = t >> 3;
    const int jp = (t & 7) * 2;
    const float al0 = alpha[j0 + jp];
    const float al1 = alpha[j0 + jp + 1];
    const size_t hrow = (size_t)(b0g + re) * HID + j0 + jp;
    float hp0 = 0.0f, hp1 = 0.0f;

    __syncthreads();   // Ws2 ready

    for (int step = 0; step < SEQ; step++) {
        // prefetch xp (L2/DRAM) before any waiting
        const size_t oidx = (size_t)step * (BATCH*HID) + hrow;
        float2 xpv = *reinterpret_cast<const float2*>(out + oidx);

        // ---- parallel stagers: warp 2c gates chunk c on its 16 producers, then bulk-copies ----
        if (is_stager) {
            const int c = mychunk;
            const float* hcur = g_h[step & 1] + (size_t)b0g * HID;
            const unsigned tgt = (unsigned)step;
            const unsigned* fb = g_flags + grp * GRP + 16 * c;
            bool ok = true;
            if (l < 16) {
                unsigned f;
                asm volatile("ld.acquire.gpu.global.u32 %0, [%1];" : "=r"(f) : "l"(fb + l) : "memory");
                ok = (f >= tgt);
            }
            while (!__all_sync(0xffffffffu, ok)) {
                if (l < 16) {
                    unsigned f;
                    asm volatile("ld.acquire.gpu.global.u32 %0, [%1];" : "=r"(f) : "l"(fb + l) : "memory");
                    ok = (f >= tgt);
                }
            }
            if (l == 0)
                asm volatile("mbarrier.arrive.expect_tx.shared.b64 _, [%0], %1;"
                             :: "r"(mbar0 + 8*c), "r"(32768u) : "memory");
            __syncwarp();
            const char* src = (const char*)(hcur + (size_t)l * HID + c * 256);
            uint32_t dst = hs_sm + (uint32_t)(c * CSLOT + l * HROW) * 4u;
            asm volatile(
                "cp.async.bulk.shared::cluster.global.mbarrier::complete_tx::bytes [%0], [%1], %2, [%3];"
                :: "r"(dst), "l"(src), "r"(1024u), "r"(mbar0 + 8*c) : "memory");
        }

        mbar_wait(mbar0 + 8 * mychunk, step & 1);

        // ---- compute: acc[4 rows][4 cols] over 128 k ----
        ull acc[4][4];
        #pragma unroll
        for (int m = 0; m < 4; m++)
            #pragma unroll
            for (int j = 0; j < 4; j++) acc[m][j] = 0ull;

        #pragma unroll 8
        for (int kq = 0; kq < 32; kq++) {
            const ull* w0 = wpB + (size_t)(2 * kq) * WSP;
            const ull* w1 = w0 + WSP;
            ulonglong2 W00 = *reinterpret_cast<const ulonglong2*>(w0);
            ulonglong2 W01 = *reinterpret_cast<const ulonglong2*>(w0 + 2);
            ulonglong2 W10 = *reinterpret_cast<const ulonglong2*>(w1);
            ulonglong2 W11 = *reinterpret_cast<const ulonglong2*>(w1 + 2);
            const float* hk = hqB + 4 * kq;
            #pragma unroll
            for (int m = 0; m < 4; m++) {
                ulonglong2 Hm = *reinterpret_cast<const ulonglong2*>(hk + m * (8 * HROW));
                acc[m][0] = ffma2(Hm.x, W00.x, acc[m][0]);
                acc[m][0] = ffma2(Hm.y, W10.x, acc[m][0]);
                acc[m][1] = ffma2(Hm.x, W00.y, acc[m][1]);
                acc[m][1] = ffma2(Hm.y, W10.y, acc[m][1]);
                acc[m][2] = ffma2(Hm.x, W01.x, acc[m][2]);
                acc[m][2] = ffma2(Hm.y, W11.x, acc[m][2]);
                acc[m][3] = ffma2(Hm.x, W01.y, acc[m][3]);
                acc[m][3] = ffma2(Hm.y, W11.y, acc[m][3]);
            }
        }

        // ---- per-warp partials -> red ----
        #pragma unroll
        for (int m = 0; m < 4; m++) {
            float2 p0 = upk(acc[m][0]);
            float2 p1 = upk(acc[m][1]);
            float2 p2 = upk(acc[m][2]);
            float2 p3 = upk(acc[m][3]);
            float4 v = make_float4(p0.x + p0.y, p1.x + p1.y, p2.x + p2.y, p3.x + p3.y);
            *reinterpret_cast<float4*>(red + w * RSP + (q + 8 * m) * 16 + 4 * jt4) = v;
        }
        __syncthreads();

        // ---- reduce 8 k-slices for this thread's 2 outputs ----
        float s0 = 0.f, s1 = 0.f;
        #pragma unroll
        for (int ww = 0; ww < 8; ww++) {
            float2 rv = *reinterpret_cast<const float2*>(red + ww * RSP + 2 * t);
            s0 += rv.x; s1 += rv.y;
        }

        // ---- gate ----
        float ht0 = tanhf(xpv.x + s0);
        float ht1 = tanhf(xpv.y + s1);
        float hn0 = hp0 + al0 * (ht0 - hp0);
        float hn1 = hp1 + al1 * (ht1 - hp1);
        hp0 = hn0; hp1 = hn1;

        // publish h_next FIRST, flag ASAP, then the output stores
        float* hnxt = g_h[(step + 1) & 1];
        *reinterpret_cast<float2*>(hnxt + hrow) = make_float2(hn0, hn1);
        __syncthreads();   // hnxt stores done block-wide; also protects red/hs reuse
        if (step < SEQ - 1 && t == 0) {
            __threadfence();
            asm volatile("st.release.gpu.global.u32 [%0], %1;"
                         :: "l"(g_flags + bid), "r"((unsigned)(step + 1)) : "memory");
        }
        *reinterpret_cast<float2*>(out + oidx) = make_float2(hn0, hn1);
        if (write_hn && step == SEQ - 1)
            *reinterpret_cast<float2*>(out + (size_t)SBH + hrow) = make_float2(hn0, hn1);
    }
}

// ---------------- launch ----------------
extern "C" void kernel_launch(void* const* d_in, const int* in_sizes, int n_in,
                              void* d_out, int out_size) {
    const float* x     = (const float*)d_in[0];   // [512,64,256]
    const float* W_in  = (const float*)d_in[1];   // [1024,256]
    const float* W_hh  = (const float*)d_in[2];   // [1024,1024]
    const float* bias  = (const float*)d_in[3];   // [1024]
    const float* alpha = (const float*)d_in[4];   // [1024]
    float* out = (float*)d_out;

    cudaFuncSetAttribute(rnn_kernel, cudaFuncAttributeMaxDynamicSharedMemorySize, SMEM_BYTES);

    init_kernel<<<(BATCH*HID + 255) / 256, 256>>>();

    dim3 g1(HID / P1_BN, (SEQ * BATCH) / P1_BM);
    xproj_kernel<<<g1, 256>>>(x, W_in, bias, out);

    int write_hn = (out_size >= SBH + BATCH * HID) ? 1 : 0;
    rnn_kernel<<<NBLK, 256, SMEM_BYTES>>>(W_hh, alpha, out, write_hn);
}

// round 13
// speedup vs baseline: 1.6134x; 1.6134x over previous
#include <cuda_runtime.h>
#include <cstdint>

typedef unsigned long long ull;

#define SEQ   512
#define BATCH 64
#define DIN   256
#define HID   1024
#define SBH   (SEQ*BATCH*HID)

// ---------------- persistent-kernel geometry ----------------
#define NBLK 128          // 64 j-tiles x 2 batch-groups, 1 block/SM
#define GRP  64           // blocks per batch group
#define BT   32           // batch rows per block
#define JT   16           // hidden cols per block
#define WSP  18           // Ws2 stride (ull) per k-pair (proven conflict-free)
#define RSP  520          // reduction slice stride (floats)
#define HROW 260          // chunk row stride (floats)
#define CSLOT (BT*HROW)   // floats per k-chunk buffer
#define NCHUNK 4

#define OFF_MBAR 0                           // 4 mbarriers
#define OFF_W    128
#define OFF_RED  (OFF_W + 512*WSP*8)         // 128 + 73728 = 73856
#define OFF_H    (OFF_RED + 8*RSP*4)         // + 16640 = 90496
#define SMEM_BYTES (OFF_H + NCHUNK*CSLOT*4)  // + 133120 = 223616

// ---------------- device state ----------------
__device__ float g_h[2][BATCH*HID];     // ping-pong hidden state (L2-resident, no init needed)
// sync words, one 128B line each: cnt[grp] @ grp*64, gen[grp] @ grp*64+32
__device__ unsigned g_sync[128];

// ---------------- f32x2 helpers ----------------
__device__ __forceinline__ ull ffma2(ull a, ull b, ull c) {
    ull d; asm("fma.rn.f32x2 %0, %1, %2, %3;" : "=l"(d) : "l"(a), "l"(b), "l"(c)); return d;
}
__device__ __forceinline__ ull pk2(float x, float y) {
    ull r; asm("mov.b64 %0, {%1, %2};" : "=l"(r) : "f"(x), "f"(y)); return r;
}
__device__ __forceinline__ float2 upk(ull v) {
    float2 r; asm("mov.b64 {%0, %1}, %2;" : "=f"(r.x), "=f"(r.y) : "l"(v)); return r;
}

// ---------------- init: sync words = 0 (g_h NOT needed: step 0 skips GEMM) ----------------
__global__ void init_kernel() {
    if (threadIdx.x < 128) g_sync[threadIdx.x] = 0u;
}

// ---------------- phase 1: xp = x @ W_in^T + bias (into d_out) ----------------
#define P1_BM 128
#define P1_BN 64
#define P1_BK 16

__global__ __launch_bounds__(256) void xproj_kernel(
        const float* __restrict__ x, const float* __restrict__ Win,
        const float* __restrict__ bias, float* __restrict__ out) {
    __shared__ ull As[P1_BM][9];
    __shared__ ull Bs[P1_BN][9];

    const int t  = threadIdx.x;
    const int m0 = blockIdx.y * P1_BM;
    const int n0 = blockIdx.x * P1_BN;
    const int tm = t >> 4;
    const int tn = t & 15;

    ull acc[8][4];
    #pragma unroll
    for (int i = 0; i < 8; i++)
        #pragma unroll
        for (int j = 0; j < 4; j++) acc[i][j] = 0ull;

    for (int k0 = 0; k0 < DIN; k0 += P1_BK) {
        #pragma unroll
        for (int l = 0; l < 2; l++) {
            int idx = t + l * 256;
            int r = idx >> 2, c = idx & 3;
            float4 v = *reinterpret_cast<const float4*>(x + (size_t)(m0 + r) * DIN + k0 + c * 4);
            As[r][c*2]   = pk2(v.x, v.y);
            As[r][c*2+1] = pk2(v.z, v.w);
        }
        {
            int r = t >> 2, c = t & 3;
            float4 v = *reinterpret_cast<const float4*>(Win + (size_t)(n0 + r) * DIN + k0 + c * 4);
            Bs[r][c*2]   = pk2(v.x, v.y);
            Bs[r][c*2+1] = pk2(v.z, v.w);
        }
        __syncthreads();
        #pragma unroll
        for (int kp = 0; kp < 8; kp++) {
            ull a[8], b[4];
            #pragma unroll
            for (int i = 0; i < 8; i++) a[i] = As[tm + 16*i][kp];
            #pragma unroll
            for (int j = 0; j < 4; j++) b[j] = Bs[tn + 16*j][kp];
            #pragma unroll
            for (int i = 0; i < 8; i++)
                #pragma unroll
                for (int j = 0; j < 4; j++)
                    acc[i][j] = ffma2(a[i], b[j], acc[i][j]);
        }
        __syncthreads();
    }
    #pragma unroll
    for (int i = 0; i < 8; i++) {
        int m = m0 + tm + 16*i;
        #pragma unroll
        for (int j = 0; j < 4; j++) {
            int n = n0 + tn + 16*j;
            float2 s = upk(acc[i][j]);
            out[(size_t)m * HID + n] = s.x + s.y + bias[n];
        }
    }
}

// ---------------- mbarrier wait ----------------
__device__ __forceinline__ void mbar_wait(uint32_t mbar, uint32_t parity) {
    uint32_t done;
    do {
        asm volatile(
            "{\n\t.reg .pred p;\n\t"
            "mbarrier.try_wait.parity.acquire.cta.shared::cta.b64 p, [%1], %2, 0x989680;\n\t"
            "selp.b32 %0, 1, 0, p;\n\t}"
            : "=r"(done) : "r"(mbar), "r"(parity) : "memory");
    } while (!done);
}

// ---------------- phase 2: persistent recurrent kernel ----------------
__global__ __launch_bounds__(256, 1) void rnn_kernel(
        const float* __restrict__ Whh, const float* __restrict__ alpha,
        float* __restrict__ out, int write_hn) {
    extern __shared__ char sm[];
    const uint32_t smb = (uint32_t)__cvta_generic_to_shared(sm);
    ull*   Ws2 = reinterpret_cast<ull*>(sm + OFF_W);
    float* red = reinterpret_cast<float*>(sm + OFF_RED);
    float* hs  = reinterpret_cast<float*>(sm + OFF_H);
    const uint32_t mbar0 = smb + OFF_MBAR;
    const uint32_t hs_sm = smb + OFF_H;

    const int t   = threadIdx.x;
    const int bid = blockIdx.x;
    const int jtb = bid & 63;
    const int grp = bid >> 6;
    const int j0  = jtb * JT;
    const int b0g = grp * BT;

    unsigned* cntp = g_sync + grp * 64;
    unsigned* genp = g_sync + grp * 64 + 32;

    if (t < NCHUNK)
        asm volatile("mbarrier.init.shared.b64 [%0], 1;" :: "r"(mbar0 + 8*t) : "memory");
    __syncthreads();

    // Load W_hh slice: Ws2[kp*WSP + jl] = {W[j0+jl][2kp], W[j0+jl][2kp+1]}
    #pragma unroll
    for (int l = 0; l < 32; l++) {
        int idx = t + l * 256;
        int jl  = idx >> 9;
        int kp  = idx & 511;
        float2 v = *reinterpret_cast<const float2*>(Whh + (size_t)(j0 + jl) * HID + 2 * kp);
        Ws2[kp * WSP + jl] = pk2(v.x, v.y);
    }

    // compute mapping: warp w = k-slice [128w,128w+128); lane -> (q rows, jt4 cols)
    const int w   = t >> 5;
    const int l   = t & 31;
    const int q   = l & 7;                 // rows q+8m
    const int jt4 = l >> 3;                // cols 4*jt4..+3
    const int mychunk = w >> 1;            // staged chunk this warp consumes
    const bool is_stager = ((w & 1) == 0); // warps 0,2,4,6 stage chunks 0..3

    const ull*   wpB = Ws2 + (size_t)w * 64 * WSP + 4 * jt4;
    const float* hqB = hs + mychunk * CSLOT + q * HROW + 128 * (w & 1);

    // epilogue mapping: 2 outputs per thread, h_prev in registers
    const int re = t >> 3;
    const int jp = (t & 7) * 2;
    const float al0 = alpha[j0 + jp];
    const float al1 = alpha[j0 + jp + 1];
    const size_t hrow = (size_t)(b0g + re) * HID + j0 + jp;
    float hp0 = 0.0f, hp1 = 0.0f;

    __syncthreads();   // Ws2 ready

    for (int step = 0; step < SEQ; step++) {
        // prefetch xp before any waiting
        const size_t oidx = (size_t)step * (BATCH*HID) + hrow;
        float2 xpv = *reinterpret_cast<const float2*>(out + oidx);

        float s0, s1;
        if (step == 0) {
            // h_prev = 0 -> GEMM term is exactly zero; no staging, no compute
            s0 = 0.0f; s1 = 0.0f;
        } else {
            // ---- stagers: wait group generation, then bulk-copy own chunk ----
            if (is_stager) {
                const int c = mychunk;
                if (l == 0) {
                    unsigned cur;
                    while (true) {
                        asm volatile("ld.acquire.gpu.global.u32 %0, [%1];"
                                     : "=r"(cur) : "l"(genp) : "memory");
                        if (cur >= (unsigned)step) break;
                        __nanosleep(64);
                    }
                    asm volatile("mbarrier.arrive.expect_tx.shared.b64 _, [%0], %1;"
                                 :: "r"(mbar0 + 8*c), "r"(32768u) : "memory");
                }
                __syncwarp();
                const float* hcur = g_h[step & 1] + (size_t)b0g * HID;
                const char* src = (const char*)(hcur + (size_t)l * HID + c * 256);
                uint32_t dst = hs_sm + (uint32_t)(c * CSLOT + l * HROW) * 4u;
                asm volatile(
                    "cp.async.bulk.shared::cluster.global.mbarrier::complete_tx::bytes [%0], [%1], %2, [%3];"
                    :: "r"(dst), "l"(src), "r"(1024u), "r"(mbar0 + 8*c) : "memory");
            }

            mbar_wait(mbar0 + 8 * mychunk, (step + 1) & 1);   // first use at step 1 -> parity 0

            // ---- compute: acc[4 rows][4 cols] over 128 k ----
            ull acc[4][4];
            #pragma unroll
            for (int m = 0; m < 4; m++)
                #pragma unroll
                for (int j = 0; j < 4; j++) acc[m][j] = 0ull;

            #pragma unroll 8
            for (int kq = 0; kq < 32; kq++) {
                const ull* w0 = wpB + (size_t)(2 * kq) * WSP;
                const ull* w1 = w0 + WSP;
                ulonglong2 W00 = *reinterpret_cast<const ulonglong2*>(w0);
                ulonglong2 W01 = *reinterpret_cast<const ulonglong2*>(w0 + 2);
                ulonglong2 W10 = *reinterpret_cast<const ulonglong2*>(w1);
                ulonglong2 W11 = *reinterpret_cast<const ulonglong2*>(w1 + 2);
                const float* hk = hqB + 4 * kq;
                #pragma unroll
                for (int m = 0; m < 4; m++) {
                    ulonglong2 Hm = *reinterpret_cast<const ulonglong2*>(hk + m * (8 * HROW));
                    acc[m][0] = ffma2(Hm.x, W00.x, acc[m][0]);
                    acc[m][0] = ffma2(Hm.y, W10.x, acc[m][0]);
                    acc[m][1] = ffma2(Hm.x, W00.y, acc[m][1]);
                    acc[m][1] = ffma2(Hm.y, W10.y, acc[m][1]);
                    acc[m][2] = ffma2(Hm.x, W01.x, acc[m][2]);
                    acc[m][2] = ffma2(Hm.y, W11.x, acc[m][2]);
                    acc[m][3] = ffma2(Hm.x, W01.y, acc[m][3]);
                    acc[m][3] = ffma2(Hm.y, W11.y, acc[m][3]);
                }
            }

            // ---- per-warp partials -> red ----
            #pragma unroll
            for (int m = 0; m < 4; m++) {
                float2 p0 = upk(acc[m][0]);
                float2 p1 = upk(acc[m][1]);
                float2 p2 = upk(acc[m][2]);
                float2 p3 = upk(acc[m][3]);
                float4 v = make_float4(p0.x + p0.y, p1.x + p1.y, p2.x + p2.y, p3.x + p3.y);
                *reinterpret_cast<float4*>(red + w * RSP + (q + 8 * m) * 16 + 4 * jt4) = v;
            }
            __syncthreads();

            // ---- reduce 8 k-slices ----
            s0 = 0.f; s1 = 0.f;
            #pragma unroll
            for (int ww = 0; ww < 8; ww++) {
                float2 rv = *reinterpret_cast<const float2*>(red + ww * RSP + 2 * t);
                s0 += rv.x; s1 += rv.y;
            }
        }

        // ---- gate ----
        float ht0 = tanhf(xpv.x + s0);
        float ht1 = tanhf(xpv.y + s1);
        float hn0 = hp0 + al0 * (ht0 - hp0);
        float hn1 = hp1 + al1 * (ht1 - hp1);
        hp0 = hn0; hp1 = hn1;

        // publish h_next, arrive at barrier ASAP, then output stores
        float* hnxt = g_h[(step + 1) & 1];
        *reinterpret_cast<float2*>(hnxt + hrow) = make_float2(hn0, hn1);
        __syncthreads();   // hnxt stores done block-wide (also protects red/hs reuse)

        if (step < SEQ - 1 && t == 0) {
            __threadfence();
            unsigned old = atomicAdd(cntp, 1u);
            if (old == GRP - 1u) {
                atomicExch(cntp, 0u);
                asm volatile("st.release.gpu.global.u32 [%0], %1;"
                             :: "l"(genp), "r"((unsigned)(step + 1)) : "memory");
            }
        }

        *reinterpret_cast<float2*>(out + oidx) = make_float2(hn0, hn1);
        if (write_hn && step == SEQ - 1)
            *reinterpret_cast<float2*>(out + (size_t)SBH + hrow) = make_float2(hn0, hn1);
    }
}

// ---------------- launch ----------------
extern "C" void kernel_launch(void* const* d_in, const int* in_sizes, int n_in,
                              void* d_out, int out_size) {
    const float* x     = (const float*)d_in[0];   // [512,64,256]
    const float* W_in  = (const float*)d_in[1];   // [1024,256]
    const float* W_hh  = (const float*)d_in[2];   // [1024,1024]
    const float* bias  = (const float*)d_in[3];   // [1024]
    const float* alpha = (const float*)d_in[4];   // [1024]
    float* out = (float*)d_out;

    cudaFuncSetAttribute(rnn_kernel, cudaFuncAttributeMaxDynamicSharedMemorySize, SMEM_BYTES);

    init_kernel<<<1, 128>>>();

    dim3 g1(HID / P1_BN, (SEQ * BATCH) / P1_BM);
    xproj_kernel<<<g1, 256>>>(x, W_in, bias, out);

    int write_hn = (out_size >= SBH + BATCH * HID) ? 1 : 0;
    rnn_kernel<<<NBLK, 256, SMEM_BYTES>>>(W_hh, alpha, out, write_hn);
}

// round 15
// speedup vs baseline: 1.6911x; 1.0482x over previous
#include <cuda_runtime.h>
#include <cstdint>

typedef unsigned long long ull;

#define SEQ   512
#define BATCH 64
#define DIN   256
#define HID   1024
#define SBH   (SEQ*BATCH*HID)

// ---------------- persistent-kernel geometry ----------------
#define NBLK 128          // 64 j-tiles x 2 batch-groups, 1 block/SM
#define GRP  64           // blocks per batch group
#define SUBG 16           // blocks per sub-barrier (j-subgroup == k-chunk producers)
#define BT   32           // batch rows per block
#define JT   16           // hidden cols per block
#define WSP  18           // Ws2 stride (ull) per k-pair (proven conflict-free)
#define RSP  520          // reduction slice stride (floats)
#define HROW 260          // chunk row stride (floats)
#define CSLOT (BT*HROW)   // floats per k-chunk buffer
#define NCHUNK 4

#define OFF_MBAR 0                           // 4 mbarriers
#define OFF_W    128
#define OFF_RED  (OFF_W + 512*WSP*8)         // 128 + 73728 = 73856
#define OFF_H    (OFF_RED + 8*RSP*4)         // + 16640 = 90496
#define SMEM_BYTES (OFF_H + NCHUNK*CSLOT*4)  // + 133120 = 223616

// ---------------- device state ----------------
__device__ float g_h[2][BATCH*HID];     // ping-pong hidden state (L2-resident, no init needed)
// 8 sub-barriers (2 groups x 4 subgroups), one 128B line each:
// cnt @ (grp*4+c)*64  (monotone), gen @ (grp*4+c)*64 + 32
__device__ unsigned g_sync[512];

// ---------------- f32x2 helpers ----------------
__device__ __forceinline__ ull ffma2(ull a, ull b, ull c) {
    ull d; asm("fma.rn.f32x2 %0, %1, %2, %3;" : "=l"(d) : "l"(a), "l"(b), "l"(c)); return d;
}
__device__ __forceinline__ ull pk2(float x, float y) {
    ull r; asm("mov.b64 %0, {%1, %2};" : "=l"(r) : "f"(x), "f"(y)); return r;
}
__device__ __forceinline__ float2 upk(ull v) {
    float2 r; asm("mov.b64 {%0, %1}, %2;" : "=f"(r.x), "=f"(r.y) : "l"(v)); return r;
}

// ---------------- init: sync words = 0 (g_h not needed: step 0 skips GEMM) ----------------
__global__ void init_kernel() {
    if (threadIdx.x < 512) g_sync[threadIdx.x] = 0u;
}

// ---------------- phase 1: xp = x @ W_in^T + bias (into d_out) ----------------
#define P1_BM 128
#define P1_BN 64
#define P1_BK 16

__global__ __launch_bounds__(256) void xproj_kernel(
        const float* __restrict__ x, const float* __restrict__ Win,
        const float* __restrict__ bias, float* __restrict__ out) {
    __shared__ ull As[P1_BM][9];
    __shared__ ull Bs[P1_BN][9];

    const int t  = threadIdx.x;
    const int m0 = blockIdx.y * P1_BM;
    const int n0 = blockIdx.x * P1_BN;
    const int tm = t >> 4;
    const int tn = t & 15;

    ull acc[8][4];
    #pragma unroll
    for (int i = 0; i < 8; i++)
        #pragma unroll
        for (int j = 0; j < 4; j++) acc[i][j] = 0ull;

    for (int k0 = 0; k0 < DIN; k0 += P1_BK) {
        #pragma unroll
        for (int l = 0; l < 2; l++) {
            int idx = t + l * 256;
            int r = idx >> 2, c = idx & 3;
            float4 v = *reinterpret_cast<const float4*>(x + (size_t)(m0 + r) * DIN + k0 + c * 4);
            As[r][c*2]   = pk2(v.x, v.y);
            As[r][c*2+1] = pk2(v.z, v.w);
        }
        {
            int r = t >> 2, c = t & 3;
            float4 v = *reinterpret_cast<const float4*>(Win + (size_t)(n0 + r) * DIN + k0 + c * 4);
            Bs[r][c*2]   = pk2(v.x, v.y);
            Bs[r][c*2+1] = pk2(v.z, v.w);
        }
        __syncthreads();
        #pragma unroll
        for (int kp = 0; kp < 8; kp++) {
            ull a[8], b[4];
            #pragma unroll
            for (int i = 0; i < 8; i++) a[i] = As[tm + 16*i][kp];
            #pragma unroll
            for (int j = 0; j < 4; j++) b[j] = Bs[tn + 16*j][kp];
            #pragma unroll
            for (int i = 0; i < 8; i++)
                #pragma unroll
                for (int j = 0; j < 4; j++)
                    acc[i][j] = ffma2(a[i], b[j], acc[i][j]);
        }
        __syncthreads();
    }
    #pragma unroll
    for (int i = 0; i < 8; i++) {
        int m = m0 + tm + 16*i;
        #pragma unroll
        for (int j = 0; j < 4; j++) {
            int n = n0 + tn + 16*j;
            float2 s = upk(acc[i][j]);
            out[(size_t)m * HID + n] = s.x + s.y + bias[n];
        }
    }
}

// ---------------- mbarrier wait ----------------
__device__ __forceinline__ void mbar_wait(uint32_t mbar, uint32_t parity) {
    uint32_t done;
    do {
        asm volatile(
            "{\n\t.reg .pred p;\n\t"
            "mbarrier.try_wait.parity.acquire.cta.shared::cta.b64 p, [%1], %2, 0x989680;\n\t"
            "selp.b32 %0, 1, 0, p;\n\t}"
            : "=r"(done) : "r"(mbar), "r"(parity) : "memory");
    } while (!done);
}

// ---------------- phase 2: persistent recurrent kernel ----------------
__global__ __launch_bounds__(256, 1) void rnn_kernel(
        const float* __restrict__ Whh, const float* __restrict__ alpha,
        float* __restrict__ out, int write_hn) {
    extern __shared__ char sm[];
    const uint32_t smb = (uint32_t)__cvta_generic_to_shared(sm);
    ull*   Ws2 = reinterpret_cast<ull*>(sm + OFF_W);
    float* red = reinterpret_cast<float*>(sm + OFF_RED);
    float* hs  = reinterpret_cast<float*>(sm + OFF_H);
    const uint32_t mbar0 = smb + OFF_MBAR;
    const uint32_t hs_sm = smb + OFF_H;

    const int t   = threadIdx.x;
    const int bid = blockIdx.x;
    const int jtb = bid & 63;
    const int grp = bid >> 6;
    const int j0  = jtb * JT;
    const int b0g = grp * BT;

    // my producer sub-barrier (arrival side)
    unsigned* cnt_my = g_sync + (grp * 4 + (jtb >> 4)) * 64;
    unsigned* gen_my = cnt_my + 32;

    if (t < NCHUNK)
        asm volatile("mbarrier.init.shared.b64 [%0], 1;" :: "r"(mbar0 + 8*t) : "memory");
    __syncthreads();

    // Load W_hh slice: Ws2[kp*WSP + jl] = {W[j0+jl][2kp], W[j0+jl][2kp+1]}
    #pragma unroll
    for (int l = 0; l < 32; l++) {
        int idx = t + l * 256;
        int jl  = idx >> 9;
        int kp  = idx & 511;
        float2 v = *reinterpret_cast<const float2*>(Whh + (size_t)(j0 + jl) * HID + 2 * kp);
        Ws2[kp * WSP + jl] = pk2(v.x, v.y);
    }

    // compute mapping: warp w = k-slice [128w,128w+128); lane -> (q rows, jt4 cols)
    const int w   = t >> 5;
    const int l   = t & 31;
    const int q   = l & 7;                 // rows q+8m
    const int jt4 = l >> 3;                // cols 4*jt4..+3
    const int mychunk = w >> 1;            // staged chunk this warp consumes
    const bool is_stager = ((w & 1) == 0); // warps 0,2,4,6 stage chunks 0..3

    // gen word of the sub-barrier whose 16 producers fill my chunk's columns
    unsigned* gen_c = g_sync + (grp * 4 + mychunk) * 64 + 32;

    const ull*   wpB = Ws2 + (size_t)w * 64 * WSP + 4 * jt4;
    const float* hqB = hs + mychunk * CSLOT + q * HROW + 128 * (w & 1);

    // epilogue mapping: 2 outputs per thread, h_prev in registers
    const int re = t >> 3;
    const int jp = (t & 7) * 2;
    const float al0 = alpha[j0 + jp];
    const float al1 = alpha[j0 + jp + 1];
    const size_t hrow = (size_t)(b0g + re) * HID + j0 + jp;
    float hp0 = 0.0f, hp1 = 0.0f;

    __syncthreads();   // Ws2 ready

    for (int step = 0; step < SEQ; step++) {
        // prefetch xp before any waiting
        const size_t oidx = (size_t)step * (BATCH*HID) + hrow;
        float2 xpv = *reinterpret_cast<const float2*>(out + oidx);

        float s0, s1;
        if (step == 0) {
            // h_prev = 0 -> GEMM term is exactly zero; no staging, no compute
            s0 = 0.0f; s1 = 0.0f;
        } else {
            // ---- stagers: wait on this chunk's 16 producers, then bulk-copy own chunk ----
            if (is_stager) {
                const int c = mychunk;
                if (l == 0) {
                    unsigned cur;
                    while (true) {
                        asm volatile("ld.acquire.gpu.global.u32 %0, [%1];"
                                     : "=r"(cur) : "l"(gen_c) : "memory");
                        if (cur >= (unsigned)step) break;
                        __nanosleep(32);
                    }
                    asm volatile("mbarrier.arrive.expect_tx.shared.b64 _, [%0], %1;"
                                 :: "r"(mbar0 + 8*c), "r"(32768u) : "memory");
                }
                __syncwarp();
                const float* hcur = g_h[step & 1] + (size_t)b0g * HID;
                const char* src = (const char*)(hcur + (size_t)l * HID + c * 256);
                uint32_t dst = hs_sm + (uint32_t)(c * CSLOT + l * HROW) * 4u;
                asm volatile(
                    "cp.async.bulk.shared::cluster.global.mbarrier::complete_tx::bytes [%0], [%1], %2, [%3];"
                    :: "r"(dst), "l"(src), "r"(1024u), "r"(mbar0 + 8*c) : "memory");
            }

            mbar_wait(mbar0 + 8 * mychunk, (step + 1) & 1);   // first use at step 1 -> parity 0

            // ---- compute: acc[4 rows][4 cols] over 128 k ----
            ull acc[4][4];
            #pragma unroll
            for (int m = 0; m < 4; m++)
                #pragma unroll
                for (int j = 0; j < 4; j++) acc[m][j] = 0ull;

            #pragma unroll 8
            for (int kq = 0; kq < 32; kq++) {
                const ull* w0 = wpB + (size_t)(2 * kq) * WSP;
                const ull* w1 = w0 + WSP;
                ulonglong2 W00 = *reinterpret_cast<const ulonglong2*>(w0);
                ulonglong2 W01 = *reinterpret_cast<const ulonglong2*>(w0 + 2);
                ulonglong2 W10 = *reinterpret_cast<const ulonglong2*>(w1);
                ulonglong2 W11 = *reinterpret_cast<const ulonglong2*>(w1 + 2);
                const float* hk = hqB + 4 * kq;
                #pragma unroll
                for (int m = 0; m < 4; m++) {
                    ulonglong2 Hm = *reinterpret_cast<const ulonglong2*>(hk + m * (8 * HROW));
                    acc[m][0] = ffma2(Hm.x, W00.x, acc[m][0]);
                    acc[m][0] = ffma2(Hm.y, W10.x, acc[m][0]);
                    acc[m][1] = ffma2(Hm.x, W00.y, acc[m][1]);
                    acc[m][1] = ffma2(Hm.y, W10.y, acc[m][1]);
                    acc[m][2] = ffma2(Hm.x, W01.x, acc[m][2]);
                    acc[m][2] = ffma2(Hm.y, W11.x, acc[m][2]);
                    acc[m][3] = ffma2(Hm.x, W01.y, acc[m][3]);
                    acc[m][3] = ffma2(Hm.y, W11.y, acc[m][3]);
                }
            }

            // ---- per-warp partials -> red ----
            #pragma unroll
            for (int m = 0; m < 4; m++) {
                float2 p0 = upk(acc[m][0]);
                float2 p1 = upk(acc[m][1]);
                float2 p2 = upk(acc[m][2]);
                float2 p3 = upk(acc[m][3]);
                float4 v = make_float4(p0.x + p0.y, p1.x + p1.y, p2.x + p2.y, p3.x + p3.y);
                *reinterpret_cast<float4*>(red + w * RSP + (q + 8 * m) * 16 + 4 * jt4) = v;
            }
            __syncthreads();

            // ---- reduce 8 k-slices ----
            s0 = 0.f; s1 = 0.f;
            #pragma unroll
            for (int ww = 0; ww < 8; ww++) {
                float2 rv = *reinterpret_cast<const float2*>(red + ww * RSP + 2 * t);
                s0 += rv.x; s1 += rv.y;
            }
        }

        // ---- gate ----
        float ht0 = tanhf(xpv.x + s0);
        float ht1 = tanhf(xpv.y + s1);
        float hn0 = hp0 + al0 * (ht0 - hp0);
        float hn1 = hp1 + al1 * (ht1 - hp1);
        hp0 = hn0; hp1 = hn1;

        // publish h_next, arrive at sub-barrier ASAP, then output stores
        float* hnxt = g_h[(step + 1) & 1];
        *reinterpret_cast<float2*>(hnxt + hrow) = make_float2(hn0, hn1);
        __syncthreads();   // hnxt stores done block-wide (also protects red/hs reuse)

        if (step < SEQ - 1 && t == 0) {
            __threadfence();
            unsigned old = atomicAdd(cnt_my, 1u);      // monotone counter, no reset
            if (old == (unsigned)(SUBG * step + (SUBG - 1))) {
                asm volatile("st.release.gpu.global.u32 [%0], %1;"
                             :: "l"(gen_my), "r"((unsigned)(step + 1)) : "memory");
            }
        }

        *reinterpret_cast<float2*>(out + oidx) = make_float2(hn0, hn1);
        if (write_hn && step == SEQ - 1)
            *reinterpret_cast<float2*>(out + (size_t)SBH + hrow) = make_float2(hn0, hn1);
    }
}

// ---------------- launch ----------------
extern "C" void kernel_launch(void* const* d_in, const int* in_sizes, int n_in,
                              void* d_out, int out_size) {
    const float* x     = (const float*)d_in[0];   // [512,64,256]
    const float* W_in  = (const float*)d_in[1];   // [1024,256]
    const float* W_hh  = (const float*)d_in[2];   // [1024,1024]
    const float* bias  = (const float*)d_in[3];   // [1024]
    const float* alpha = (const float*)d_in[4];   // [1024]
    float* out = (float*)d_out;

    cudaFuncSetAttribute(rnn_kernel, cudaFuncAttributeMaxDynamicSharedMemorySize, SMEM_BYTES);

    init_kernel<<<1, 512>>>();

    dim3 g1(HID / P1_BN, (SEQ * BATCH) / P1_BM);
    xproj_kernel<<<g1, 256>>>(x, W_in, bias, out);

    int write_hn = (out_size >= SBH + BATCH * HID) ? 1 : 0;
    rnn_kernel<<<NBLK, 256, SMEM_BYTES>>>(W_hh, alpha, out, write_hn);
}